// round 15
// baseline (speedup 1.0000x reference)
#include <cuda_runtime.h>
#include <math.h>

#define NB 512
#define NBINS 20
#define K_CHEB 12
#define TPB 256
#define GRID 2664             // divisible by 4: 1998 hist CTAs + 666 cheb CTAs
#define NCTA_H 1998
#define NCTA_C 666

// g_acc layout: [0..19] hist A~_j, [20..39] hist D~_j,
//               [40..51] cheb M~_k (k=1..12), [52..64] cheb N~_k (k=0..12)
#define NACC 65

#define CNT_INC (1u << 24)
#define SUM_MASK 0xFFFFFFu
#define DS_SCALE 16384.0f     // 2^14
#define DS_INV (1.0f / 16384.0f)
#define DS_BIAS 32768         // 2^15 per element

__device__ double g_acc[NACC];
__device__ unsigned int g_count;

__device__ __forceinline__ float wred_f(float v) {
#pragma unroll
    for (int off = 16; off; off >>= 1)
        v += __shfl_down_sync(0xffffffffu, v, off);
    return v;
}
__device__ __forceinline__ double wred_d(double v) {
#pragma unroll
    for (int off = 16; off; off >>= 1)
        v += __shfl_down_sync(0xffffffffu, v, off);
    return v;
}

__global__ void __launch_bounds__(TPB, 6)
ace_split_kernel(const float* __restrict__ preds,
                 const float* __restrict__ targs,
                 int n, float* __restrict__ out, int out_size) {
    __shared__ unsigned int hist[NB];
    __shared__ float sh[TPB / 32][40];
    __shared__ float smA[NBINS], smD[NBINS];

    const int tid = threadIdx.x;
    const int lane = tid & 31;
    const int warp = tid >> 5;
    const int bid = blockIdx.x;
    const bool is_hist = (bid & 3) < 3;

    const int n4 = n >> 2;
    const int n4h = (int)(((long long)n4 * 3) >> 2);   // hist: [0,n4h), cheb: [n4h,n4)
    const float4* p4 = (const float4*)preds;
    const float4* t4 = (const float4*)targs;

    if (is_hist) {
        // ================= HIST PATH (R13 core) =================
        for (int b = tid; b < NB; b += TPB) hist[b] = 0u;
        if (tid < NBINS) { smA[tid] = 0.0f; smD[tid] = 0.0f; }
        __syncthreads();

        const int rank = (bid >> 2) * 3 + (bid & 3);
        const int stride = NCTA_H * TPB;
        int g = rank * TPB + tid;

        if (g < n4h) {
            float4 pv = p4[g];
            float4 tv = t4[g];
            while (1) {
                int gn = g + stride;
                bool more = (gn < n4h);
                float4 pn, tn;
                if (more) { pn = p4[gn]; tn = t4[gn]; }

#pragma unroll
                for (int e = 0; e < 4; e++) {
                    float p = (e == 0) ? pv.x : (e == 1) ? pv.y : (e == 2) ? pv.z : pv.w;
                    float t = (e == 0) ? tv.x : (e == 1) ? tv.y : (e == 2) ? tv.z : tv.w;
                    int b = (int)(p * (float)NB);
                    b = min(max(b, 0), NB - 1);
                    int ds = __float2int_rn((p - t) * DS_SCALE);
                    atomicAdd(&hist[b], CNT_INC + (unsigned int)(ds + DS_BIAS));
                }
                if (!more) break;
                pv = pn; tv = tn; g = gn;
            }
        }

        // scalar tail (n % 4) -> hist CTA 0
        {
            int base4 = n4 << 2;
            int rem = n - base4;
            if (bid == 0 && tid < rem) {
                float p = preds[base4 + tid];
                float t = targs[base4 + tid];
                int b = min(max((int)(p * (float)NB), 0), NB - 1);
                int ds = __float2int_rn((p - t) * DS_SCALE);
                atomicAdd(&hist[b], CNT_INC + (unsigned int)(ds + DS_BIAS));
            }
        }
        __syncthreads();

        // fold 512-bin histogram into 40 moments (2 bins/thread)
        {
            int b0 = tid;
            int b1 = tid + TPB;
            unsigned int v0 = hist[b0];
            unsigned int v1 = hist[b1];
            float cnt0 = (float)(v0 >> 24);
            float cnt1 = (float)(v1 >> 24);
            float Dv0 = ((float)(int)((v0 & SUM_MASK) - ((v0 >> 24) << 15))) * DS_INV;
            float Dv1 = ((float)(int)((v1 & SUM_MASK) - ((v1 >> 24) << 15))) * DS_INV;
            float c0 = ((float)b0 + 0.5f) * (1.0f / (float)NB);
            float c1 = ((float)b1 + 0.5f) * (1.0f / (float)NB);
            float w0   = __expf(-10.0f * c0 * c0);
            float w1   = __expf(-10.0f * c1 * c1);
            float rho0 = __expf(c0 * (20.0f / 19.0f));
            float rho1 = __expf(c1 * (20.0f / 19.0f));

#pragma unroll
            for (int j = 0; j < NBINS; j++) {
                float a = wred_f(fmaf(w0, cnt0, w1 * cnt1));
                float d = wred_f(fmaf(w0, Dv0, w1 * Dv1));
                if (lane == 0) { atomicAdd(&smA[j], a); atomicAdd(&smD[j], d); }
                w0 *= rho0;
                w1 *= rho1;
            }
        }
        __syncthreads();

        if (tid < 40) {
            double v = (tid < NBINS) ? (double)smA[tid] : (double)smD[tid - NBINS];
            atomicAdd(&g_acc[tid], v);
        }
    } else {
        // ================= CHEB PATH (R9 core, LDG prefetch) =================
        float M[K_CHEB], N[K_CHEB + 1];
#pragma unroll
        for (int j = 0; j < K_CHEB; j++) M[j] = 0.0f;
#pragma unroll
        for (int j = 0; j <= K_CHEB; j++) N[j] = 0.0f;

        const int rank = bid >> 2;
        const int stride = NCTA_C * TPB;
        int g = n4h + rank * TPB + tid;

        if (g < n4) {
            float4 pv = p4[g];
            float4 tv = t4[g];
            while (1) {
                int gn = g + stride;
                bool more = (gn < n4);
                float4 pn, tn;
                if (more) { pn = p4[gn]; tn = t4[gn]; }

#pragma unroll
                for (int e = 0; e < 4; e++) {
                    float p = (e == 0) ? pv.x : (e == 1) ? pv.y : (e == 2) ? pv.z : pv.w;
                    float t = (e == 0) ? tv.x : (e == 1) ? tv.y : (e == 2) ? tv.z : tv.w;
                    float u   = fmaf(2.0f, p, -1.0f);
                    float d   = p - t;
                    float u2  = u + u;
                    float nu2 = -u2;

                    N[0] += d;
                    M[0] += u;
                    N[1] = fmaf(u, d, N[1]);
                    float Sp = 1.0f, Sc = u;
#pragma unroll
                    for (int k = 2; k <= K_CHEB; k++) {
                        float Sn = fmaf((k & 1) ? u2 : nu2, Sc, Sp);
                        Sp = Sc; Sc = Sn;
                        M[k - 1] += Sc;
                        N[k] = fmaf(Sc, d, N[k]);
                    }
                }
                if (!more) break;
                pv = pn; tv = tn; g = gn;
            }
        }
        __syncthreads();   // pair with hist path's barrier count? (see note below)

#pragma unroll
        for (int k = 0; k < 2 * K_CHEB + 1; k++) {
            float s = wred_f((k < K_CHEB) ? M[k] : N[k - K_CHEB]);
            if (lane == 0) sh[warp][k] = s;
        }
        __syncthreads();

        if (tid < 2 * K_CHEB + 1) {
            double v = 0.0;
#pragma unroll
            for (int w2 = 0; w2 < TPB / 32; w2++) v += (double)sh[w2][tid];
            atomicAdd(&g_acc[40 + tid], v);
        }
    }
    __syncthreads();

    // ---- last CTA finalizes ----
    __shared__ unsigned int s_is_last;
    if (tid == 0) {
        __threadfence();
        unsigned int old = atomicAdd(&g_count, 1u);
        s_is_last = (old == gridDim.x - 1) ? 1u : 0u;
    }
    __syncthreads();

    if (s_is_last) {
        __shared__ double mAcc[NACC];
        __shared__ double sA[NBINS], sD[NBINS];
        if (tid < NACC) { __threadfence(); mAcc[tid] = atomicAdd(&g_acc[tid], 0.0); }
        if (tid < NBINS) { sA[tid] = 0.0; sD[tid] = 0.0; }
        __syncthreads();

        // Chebyshev reconstruction via 128-node quadrature (threads 0..127)
        if (tid < 128) {
            const double PI_D = 3.14159265358979323846;
            double theta = (tid + 0.5) * (PI_D / 128.0);
            double um = cos(theta);
            double n_c = (double)((n4 - n4h) * 4);   // cheb element count (M_0)
            double G = n_c;
            double H = mAcc[40 + K_CHEB];            // N_0
#pragma unroll
            for (int k = 1; k <= K_CHEB; k++) {
                double sg = ((k >> 1) & 1) ? -1.0 : 1.0;
                double ck = 2.0 * cos(k * theta) * sg;
                G += ck * mAcc[40 + k - 1];
                H += ck * mAcc[40 + K_CHEB + k];
            }
            G *= (1.0 / 128.0);
            H *= (1.0 / 128.0);
            double pm = 0.5 * (um + 1.0);

            for (int j = 0; j < NBINS; j++) {
                double cj = (double)j / 19.0;
                double w = exp(-10.0 * (pm - cj) * (pm - cj));
                double a = wred_d(w * G);
                double d = wred_d(w * H);
                if (lane == 0) { atomicAdd(&sA[j], a); atomicAdd(&sD[j], d); }
            }
        }
        __syncthreads();

        if (tid == 0) {
            double loss = 0.0;
            for (int j = 0; j < NBINS; j++) {
                double cj = (double)j / 19.0;
                double kappa = exp(-10.0 * cj * cj);
                double Aj = kappa * mAcc[j]        + sA[j];
                double Dj = kappa * mAcc[NBINS + j] + sD[j];
                if (Aj != 0.0) loss += fabs(Dj) / (Aj + 1e-8);
            }
            float res = (float)(loss / NBINS);
            for (int i = 0; i < out_size; i++) out[i] = res;
            for (int k = 0; k < NACC; k++) g_acc[k] = 0.0;
            g_count = 0u;
            __threadfence();
        }
    }
}

extern "C" void kernel_launch(void* const* d_in, const int* in_sizes, int n_in,
                              void* d_out, int out_size) {
    const float* preds = (const float*)d_in[0];
    const float* targs = (const float*)d_in[1];
    int n = in_sizes[0];
    ace_split_kernel<<<GRID, TPB>>>(preds, targs, n, (float*)d_out, out_size);
}

// round 16
// speedup vs baseline: 1.0703x; 1.0703x over previous
#include <cuda_runtime.h>
#include <math.h>

#define NB 512
#define NBINS 20
#define K_CHEB 12
#define TPB 256
#define GRID (148 * 4 * 3)    // 4 CTAs/SM (64-reg budget), 3 waves

// g_acc layout: [0..19] hist A~_j, [20..39] hist D~_j,
//               [40..51] cheb M~_k (k=1..12), [52..64] cheb N~_k (k=0..12)
#define NACC 65

#define CNT_INC (1u << 24)
#define SUM_MASK 0xFFFFFFu
#define DS_SCALE 16384.0f     // 2^14
#define DS_INV (1.0f / 16384.0f)
#define DS_BIAS 32768         // 2^15 per element

__device__ double g_acc[NACC];
__device__ unsigned int g_count;

__device__ __forceinline__ float wred_f(float v) {
#pragma unroll
    for (int off = 16; off; off >>= 1)
        v += __shfl_down_sync(0xffffffffu, v, off);
    return v;
}
__device__ __forceinline__ double wred_d(double v) {
#pragma unroll
    for (int off = 16; off; off >>= 1)
        v += __shfl_down_sync(0xffffffffu, v, off);
    return v;
}

__global__ void __launch_bounds__(TPB, 4)
ace_dual_kernel(const float* __restrict__ preds,
                const float* __restrict__ targs,
                int n, float* __restrict__ out, int out_size) {
    __shared__ unsigned int hist[NB];
    __shared__ float sh[TPB / 32][25];
    __shared__ float smA[NBINS], smD[NBINS];

    const int tid = threadIdx.x;
    const int lane = tid & 31;
    const int warp = tid >> 5;

    for (int b = tid; b < NB; b += TPB) hist[b] = 0u;
    if (tid < NBINS) { smA[tid] = 0.0f; smD[tid] = 0.0f; }

    // Chebyshev accumulators: M[k-1] = sum S_k (k=1..12), N[k] = sum S_k*d (k=0..12)
    float M[K_CHEB], N[K_CHEB + 1];
#pragma unroll
    for (int j = 0; j < K_CHEB; j++) M[j] = 0.0f;
#pragma unroll
    for (int j = 0; j <= K_CHEB; j++) N[j] = 0.0f;

    __syncthreads();

    const int n4 = n >> 2;
    const int n4h = n4 >> 1;             // hist half: [0, n4h), cheb half: [n4h, n4)
    const float4* p4 = (const float4*)preds;
    const float4* t4 = (const float4*)targs;
    const int strideT = GRID * TPB;
    const int g0 = blockIdx.x * TPB + tid;

    const int cntH = (g0 < n4h) ? ((n4h - 1 - g0) / strideT + 1) : 0;
    const int cntC = (g0 + n4h < n4) ? ((n4 - 1 - (g0 + n4h)) / strideT + 1) : 0;
    const int cnt = (cntH > cntC) ? cntH : cntC;

    for (int i = 0; i < cnt; i++) {
        int gh = g0 + i * strideT;
        int gc = gh + n4h;
        bool doH = (i < cntH);
        bool doC = (i < cntC);

        float4 pvh, tvh, pvc, tvc;
        if (doH) { pvh = p4[gh]; tvh = t4[gh]; }
        if (doC) { pvc = p4[gc]; tvc = t4[gc]; }

        // ---- hist element group: 4 REDS.32 (LSU backend) ----
        if (doH) {
#pragma unroll
            for (int e = 0; e < 4; e++) {
                float p = (e == 0) ? pvh.x : (e == 1) ? pvh.y : (e == 2) ? pvh.z : pvh.w;
                float t = (e == 0) ? tvh.x : (e == 1) ? tvh.y : (e == 2) ? tvh.z : tvh.w;
                int b = (int)(p * (float)NB);
                b = min(max(b, 0), NB - 1);
                int ds = __float2int_rn((p - t) * DS_SCALE);
                atomicAdd(&hist[b], CNT_INC + (unsigned int)(ds + DS_BIAS));
            }
        }

        // ---- cheb element group: pure FFMA stream (fma backend) ----
        if (doC) {
#pragma unroll
            for (int e = 0; e < 4; e++) {
                float p = (e == 0) ? pvc.x : (e == 1) ? pvc.y : (e == 2) ? pvc.z : pvc.w;
                float t = (e == 0) ? tvc.x : (e == 1) ? tvc.y : (e == 2) ? tvc.z : tvc.w;
                float u   = fmaf(2.0f, p, -1.0f);
                float d   = p - t;
                float u2  = u + u;
                float nu2 = -u2;

                N[0] += d;
                M[0] += u;
                N[1] = fmaf(u, d, N[1]);
                float Sp = 1.0f, Sc = u;
#pragma unroll
                for (int k = 2; k <= K_CHEB; k++) {
                    float Sn = fmaf((k & 1) ? u2 : nu2, Sc, Sp);
                    Sp = Sc; Sc = Sn;
                    M[k - 1] += Sc;
                    N[k] = fmaf(Sc, d, N[k]);
                }
            }
        }
    }

    // ---- scalar tail (n % 4): CTA 0 folds into its histogram ----
    {
        int base4 = n4 << 2;
        int rem = n - base4;
        if (blockIdx.x == 0 && tid < rem) {
            float p = preds[base4 + tid];
            float t = targs[base4 + tid];
            int b = min(max((int)(p * (float)NB), 0), NB - 1);
            int ds = __float2int_rn((p - t) * DS_SCALE);
            atomicAdd(&hist[b], CNT_INC + (unsigned int)(ds + DS_BIAS));
        }
    }
    __syncthreads();

    // ---- epilogue A: fold 512-bin histogram into 40 moments (2 bins/thread) ----
    {
        int b0 = tid;
        int b1 = tid + TPB;
        unsigned int v0 = hist[b0];
        unsigned int v1 = hist[b1];
        float cnt0 = (float)(v0 >> 24);
        float cnt1 = (float)(v1 >> 24);
        float Dv0 = ((float)(int)((v0 & SUM_MASK) - ((v0 >> 24) << 15))) * DS_INV;
        float Dv1 = ((float)(int)((v1 & SUM_MASK) - ((v1 >> 24) << 15))) * DS_INV;
        float c0 = ((float)b0 + 0.5f) * (1.0f / (float)NB);
        float c1 = ((float)b1 + 0.5f) * (1.0f / (float)NB);
        float w0   = __expf(-10.0f * c0 * c0);
        float w1   = __expf(-10.0f * c1 * c1);
        float rho0 = __expf(c0 * (20.0f / 19.0f));
        float rho1 = __expf(c1 * (20.0f / 19.0f));

#pragma unroll
        for (int j = 0; j < NBINS; j++) {
            float a = wred_f(fmaf(w0, cnt0, w1 * cnt1));
            float d = wred_f(fmaf(w0, Dv0, w1 * Dv1));
            if (lane == 0) { atomicAdd(&smA[j], a); atomicAdd(&smD[j], d); }
            w0 *= rho0;
            w1 *= rho1;
        }
    }

    // ---- epilogue B: reduce cheb moments ----
#pragma unroll
    for (int k = 0; k < 2 * K_CHEB + 1; k++) {
        float s = wred_f((k < K_CHEB) ? M[k] : N[k - K_CHEB]);
        if (lane == 0) sh[warp][k] = s;
    }
    __syncthreads();

    if (tid < 40) {
        double v = (tid < NBINS) ? (double)smA[tid] : (double)smD[tid - NBINS];
        atomicAdd(&g_acc[tid], v);
    }
    if (tid < 2 * K_CHEB + 1) {
        double v = 0.0;
#pragma unroll
        for (int w2 = 0; w2 < TPB / 32; w2++) v += (double)sh[w2][tid];
        atomicAdd(&g_acc[40 + tid], v);
    }
    __syncthreads();

    // ---- last CTA finalizes ----
    __shared__ unsigned int s_is_last;
    if (tid == 0) {
        __threadfence();
        unsigned int old = atomicAdd(&g_count, 1u);
        s_is_last = (old == gridDim.x - 1) ? 1u : 0u;
    }
    __syncthreads();

    if (s_is_last) {
        __shared__ double mAcc[NACC];
        __shared__ double sA[NBINS], sD[NBINS];
        if (tid < NACC) { __threadfence(); mAcc[tid] = atomicAdd(&g_acc[tid], 0.0); }
        if (tid < NBINS) { sA[tid] = 0.0; sD[tid] = 0.0; }
        __syncthreads();

        // Chebyshev reconstruction via 128-node quadrature (threads 0..127)
        if (tid < 128) {
            const double PI_D = 3.14159265358979323846;
            double theta = (tid + 0.5) * (PI_D / 128.0);
            double um = cos(theta);
            double n_c = (double)((n4 - n4h) * 4);   // cheb element count (M_0)
            double G = n_c;
            double H = mAcc[40 + K_CHEB];            // N_0
#pragma unroll
            for (int k = 1; k <= K_CHEB; k++) {
                double sg = ((k >> 1) & 1) ? -1.0 : 1.0;
                double ck = 2.0 * cos(k * theta) * sg;
                G += ck * mAcc[40 + k - 1];
                H += ck * mAcc[40 + K_CHEB + k];
            }
            G *= (1.0 / 128.0);
            H *= (1.0 / 128.0);
            double pm = 0.5 * (um + 1.0);

            for (int j = 0; j < NBINS; j++) {
                double cj = (double)j / 19.0;
                double w = exp(-10.0 * (pm - cj) * (pm - cj));
                double a = wred_d(w * G);
                double d = wred_d(w * H);
                if (lane == 0) { atomicAdd(&sA[j], a); atomicAdd(&sD[j], d); }
            }
        }
        __syncthreads();

        if (tid == 0) {
            double loss = 0.0;
            for (int j = 0; j < NBINS; j++) {
                double cj = (double)j / 19.0;
                double kappa = exp(-10.0 * cj * cj);
                double Aj = kappa * mAcc[j]         + sA[j];
                double Dj = kappa * mAcc[NBINS + j] + sD[j];
                if (Aj != 0.0) loss += fabs(Dj) / (Aj + 1e-8);
            }
            float res = (float)(loss / NBINS);
            for (int i = 0; i < out_size; i++) out[i] = res;
            for (int k = 0; k < NACC; k++) g_acc[k] = 0.0;
            g_count = 0u;
            __threadfence();
        }
    }
}

extern "C" void kernel_launch(void* const* d_in, const int* in_sizes, int n_in,
                              void* d_out, int out_size) {
    const float* preds = (const float*)d_in[0];
    const float* targs = (const float*)d_in[1];
    int n = in_sizes[0];
    ace_dual_kernel<<<GRID, TPB>>>(preds, targs, n, (float*)d_out, out_size);
}